// round 5
// baseline (speedup 1.0000x reference)
#include <cuda_runtime.h>
#include <stdint.h>

// x:   [B=32, T=256, HW=3136] fp32 (exact 0.0/1.0 values)
// idx: [C=64, k=4] int32 in [0,256)
// out: [B, C=64, HW] fp32 = (x[e0]+x[e1]+x[e2]+x[e3] >= 2) ? 1 : 0
#define B_    32
#define T_    256
#define HW_   3136
#define C_    64
#define NGRP  25               // ceil(3136/128) position groups of 128 floats

// Fused single kernel, split 2x along channels vs R4:
// block (256 thr) owns (b, g, half): 128 positions x 32 output channels.
// Grid = 32*25*2 = 1600 blocks. Both halves of a (b,g) pair reuse the same
// ~162 unique gather rows (83 KB) through L1/L2, so DRAM traffic is unchanged
// (65 MB unique reads + 25.7 MB writes); TLP doubles and the partial-wave
// tail halves.
__global__ void __launch_bounds__(256)
rp_fused(const float* __restrict__ x, const int* __restrict__ idx,
         float* __restrict__ out) {
    __shared__ int s_idx[C_ * 4];

    const int tid  = threadIdx.x;
    const int warp = tid >> 5;
    const int lane = tid & 31;

    s_idx[tid] = __ldg(idx + tid);          // 256 routing entries
    __syncthreads();

    const int blk  = blockIdx.x;            // 1600 = 32 * 25 * 2
    const int half = blk & 1;
    const int bg   = blk >> 1;
    const int b    = bg / NGRP;
    const int g    = bg - b * NGRP;
    const int pos  = g * 128 + lane * 4;
    const bool ok  = (pos < HW_);           // tail group g=24: 64 valid pos

    const float* xb = x   + ((size_t)b * T_) * HW_ + pos;
    float*       ob = out + ((size_t)b * C_) * HW_ + pos;

    const int cbase = half * 32 + warp * 4; // 4 channels per warp

    // 2 channels per inner step -> 8 independent LDG.128 in flight per thread.
    #pragma unroll
    for (int j0 = 0; j0 < 4; j0 += 2) {
        float4 v[2][4];
        #pragma unroll
        for (int u = 0; u < 2; u++) {
            const int c  = cbase + j0 + u;
            const int e0 = s_idx[c * 4 + 0];
            const int e1 = s_idx[c * 4 + 1];
            const int e2 = s_idx[c * 4 + 2];
            const int e3 = s_idx[c * 4 + 3];
            if (ok) {
                v[u][0] = *(const float4*)(xb + (size_t)e0 * HW_);
                v[u][1] = *(const float4*)(xb + (size_t)e1 * HW_);
                v[u][2] = *(const float4*)(xb + (size_t)e2 * HW_);
                v[u][3] = *(const float4*)(xb + (size_t)e3 * HW_);
            }
        }
        #pragma unroll
        for (int u = 0; u < 2; u++) {
            const int c = cbase + j0 + u;
            if (ok) {
                float4 r;
                r.x = ((v[u][0].x + v[u][1].x) + (v[u][2].x + v[u][3].x) >= 2.0f) ? 1.0f : 0.0f;
                r.y = ((v[u][0].y + v[u][1].y) + (v[u][2].y + v[u][3].y) >= 2.0f) ? 1.0f : 0.0f;
                r.z = ((v[u][0].z + v[u][1].z) + (v[u][2].z + v[u][3].z) >= 2.0f) ? 1.0f : 0.0f;
                r.w = ((v[u][0].w + v[u][1].w) + (v[u][2].w + v[u][3].w) >= 2.0f) ? 1.0f : 0.0f;
                *(float4*)(ob + (size_t)c * HW_) = r;
            }
        }
    }
}

extern "C" void kernel_launch(void* const* d_in, const int* in_sizes, int n_in,
                              void* d_out, int out_size) {
    const float* x   = (const float*)d_in[0];
    const int*   idx = (const int*)  d_in[1];
    float*       out = (float*)d_out;
    (void)in_sizes; (void)n_in; (void)out_size;

    rp_fused<<<B_ * NGRP * 2, 256>>>(x, idx, out);   // 1600 blocks
}

// round 6
// speedup vs baseline: 1.1546x; 1.1546x over previous
#include <cuda_runtime.h>
#include <stdint.h>

// x:   [B=32, T=256, HW=3136] fp32 (exact 0.0/1.0 values)
// idx: [C=64, k=4] int32 in [0,256)
// out: [B, C=64, HW] fp32 = (x[e0]+x[e1]+x[e2]+x[e3] >= 2) ? 1 : 0
#define B_    32
#define T_    256
#define HW_   3136
#define C_    64
#define NGRP  25               // ceil(3136/128) position groups of 128 floats

// R4 structure (best: 13.2us, DRAM-bound 55%): block (256 thr) owns (b, g):
// 128 positions x all 64 output channels. ~162 unique gather rows (83 KB)
// per (b,g) are touched by exactly one block -> repeats hit L1/L2; DRAM sees
// only unique reads (65 MB) + writes (25.7 MB). Single wave: 800 CTAs fit
// in 148 SMs x 6 blocks. Stores are streaming (__stcs): output is never
// re-read, keep L2 for the gather reuse path.
__global__ void __launch_bounds__(256)
rp_fused(const float* __restrict__ x, const int* __restrict__ idx,
         float* __restrict__ out) {
    __shared__ int s_idx[C_ * 4];

    const int tid  = threadIdx.x;
    const int warp = tid >> 5;
    const int lane = tid & 31;

    s_idx[tid] = __ldg(idx + tid);          // 256 routing entries
    __syncthreads();

    const int blk = blockIdx.x;             // 800 = 32 * 25
    const int b   = blk / NGRP;
    const int g   = blk - b * NGRP;
    const int pos = g * 128 + lane * 4;
    const bool ok = (pos < HW_);            // tail group g=24: 64 valid pos

    const float* xb = x   + ((size_t)b * T_) * HW_ + pos;
    float*       ob = out + ((size_t)b * C_) * HW_ + pos;

    // Warp computes 8 contiguous channels; 2 channels per inner step ->
    // 8 independent LDG.128 in flight per thread (ample MLP).
    #pragma unroll
    for (int j0 = 0; j0 < 8; j0 += 2) {
        float4 v[2][4];
        #pragma unroll
        for (int u = 0; u < 2; u++) {
            const int c  = warp * 8 + j0 + u;
            const int e0 = s_idx[c * 4 + 0];
            const int e1 = s_idx[c * 4 + 1];
            const int e2 = s_idx[c * 4 + 2];
            const int e3 = s_idx[c * 4 + 3];
            if (ok) {
                v[u][0] = *(const float4*)(xb + (size_t)e0 * HW_);
                v[u][1] = *(const float4*)(xb + (size_t)e1 * HW_);
                v[u][2] = *(const float4*)(xb + (size_t)e2 * HW_);
                v[u][3] = *(const float4*)(xb + (size_t)e3 * HW_);
            }
        }
        #pragma unroll
        for (int u = 0; u < 2; u++) {
            const int c = warp * 8 + j0 + u;
            if (ok) {
                float4 r;
                r.x = ((v[u][0].x + v[u][1].x) + (v[u][2].x + v[u][3].x) >= 2.0f) ? 1.0f : 0.0f;
                r.y = ((v[u][0].y + v[u][1].y) + (v[u][2].y + v[u][3].y) >= 2.0f) ? 1.0f : 0.0f;
                r.z = ((v[u][0].z + v[u][1].z) + (v[u][2].z + v[u][3].z) >= 2.0f) ? 1.0f : 0.0f;
                r.w = ((v[u][0].w + v[u][1].w) + (v[u][2].w + v[u][3].w) >= 2.0f) ? 1.0f : 0.0f;
                __stcs((float4*)(ob + (size_t)c * HW_), r);
            }
        }
    }
}

extern "C" void kernel_launch(void* const* d_in, const int* in_sizes, int n_in,
                              void* d_out, int out_size) {
    const float* x   = (const float*)d_in[0];
    const int*   idx = (const int*)  d_in[1];
    float*       out = (float*)d_out;
    (void)in_sizes; (void)n_in; (void)out_size;

    rp_fused<<<B_ * NGRP, 256>>>(x, idx, out);   // 800 blocks, single wave
}